// round 2
// baseline (speedup 1.0000x reference)
#include <cuda_runtime.h>

// MaxPoolingMatching: out[b,l,p] = max_m cos( s1[b,l]*k[p], s2[b,m]*k[p] )
// Restructured:
//   num[b,l,m,p] = sum_d s1[b,l,d]*s2[b,m,d]*k[p,d]^2
//   n1inv[b,l,p] = rsqrt(max(sum_d (s1*k)^2, 1e-12)), same for n2inv
//   out[b,l,p]   = n1inv[b,l,p] * max_m ( num * n2inv[b,m,p] )
// => 320 fused 256x256x256 fp32 GEMMs with scale+max epilogue.

#define NB 16
#define NL 256
#define ND 256
#define NP 20

#define TILE 128
#define KSTEP 8
#define SPAD 4   // smem row pad (floats)

__device__ float g_n1inv[NB * NL * NP];
__device__ float g_n2inv[NB * NL * NP];

// ---------------------------------------------------------------------------
// Kernel 1: inverse norms.  One warp per row (row = (b,l) of sent1 or sent2).
// k (20x256 = 20KB) staged in smem per block and reused by all 8 warps.
// ---------------------------------------------------------------------------
__global__ void __launch_bounds__(256) norms_kernel(
    const float* __restrict__ s1,
    const float* __restrict__ s2,
    const float* __restrict__ kern)
{
    __shared__ float sk[NP * ND];  // 20 KB
    const int tid = threadIdx.x;
    for (int i = 0; i < 20; ++i)
        sk[i * 256 + tid] = kern[i * 256 + tid];
    __syncthreads();

    const int lane = tid & 31;
    const int warp = tid >> 5;
    const int row  = blockIdx.x * 8 + warp;       // 0 .. 2*NB*NL-1
    const int NR   = NB * NL;

    const float* src = (row < NR) ? (s1 + (size_t)row * ND)
                                  : (s2 + (size_t)(row - NR) * ND);
    float* dst = (row < NR) ? (g_n1inv + (size_t)row * NP)
                            : (g_n2inv + (size_t)(row - NR) * NP);

    // 8 elements / lane: d = lane*4 .. +3  and  128 + lane*4 .. +3
    const float4 v0 = *reinterpret_cast<const float4*>(src + lane * 4);
    const float4 v1 = *reinterpret_cast<const float4*>(src + 128 + lane * 4);

    for (int p = 0; p < NP; ++p) {
        const float* kp = sk + p * ND;
        const float4 k0 = *reinterpret_cast<const float4*>(kp + lane * 4);
        const float4 k1 = *reinterpret_cast<const float4*>(kp + 128 + lane * 4);
        float s = 0.f, t;
        t = v0.x * k0.x; s = fmaf(t, t, s);
        t = v0.y * k0.y; s = fmaf(t, t, s);
        t = v0.z * k0.z; s = fmaf(t, t, s);
        t = v0.w * k0.w; s = fmaf(t, t, s);
        t = v1.x * k1.x; s = fmaf(t, t, s);
        t = v1.y * k1.y; s = fmaf(t, t, s);
        t = v1.z * k1.z; s = fmaf(t, t, s);
        t = v1.w * k1.w; s = fmaf(t, t, s);
        #pragma unroll
        for (int o = 16; o > 0; o >>= 1)
            s += __shfl_xor_sync(0xffffffffu, s, o);
        if (lane == 0)
            dst[p] = rsqrtf(fmaxf(s, 1e-12f));
    }
}

// ---------------------------------------------------------------------------
// Kernel 2: fused weighted GEMM + scale + row-max.
// grid = (l_tiles=2, P=20, B=16); block = 256 threads.
// Block computes a 128(l) x 128(m) product tile for one (b,p), loops both
// m-tiles, keeps running max_m( C[l,m] * n2inv[b,m,p] ) and writes
// out[b,l,p] = rowmax * n1inv[b,l,p].
// B-operand is scaled by k[p,d]^2 while staging to smem.
// Microtile 8x8 per thread with split-tile mapping (tx*4 and 64+tx*4)
// for conflict-free LDS.128.
// ---------------------------------------------------------------------------
__global__ void __launch_bounds__(256, 2) mpm_kernel(
    const float* __restrict__ s1,
    const float* __restrict__ s2,
    const float* __restrict__ kern,
    float* __restrict__ out)
{
    __shared__ float As[KSTEP][TILE + SPAD];
    __shared__ float Bs[KSTEP][TILE + SPAD];

    const int b  = blockIdx.z;
    const int p  = blockIdx.y;
    const int l0 = blockIdx.x * TILE;

    const int tid = threadIdx.x;
    const int tx  = tid & 15;
    const int ty  = tid >> 4;

    // loader mapping: 256 threads load 128 rows x 8 d (one float4 each)
    const int ldl = tid >> 1;          // row within tile 0..127
    const int ldv = (tid & 1) * 4;     // d offset 0 or 4

    const float* A_base = s1 + ((size_t)(b * NL + l0 + ldl)) * ND + ldv;
    const float* kp     = kern + p * ND + ldv;

    const float NEG_INF = __int_as_float(0xff800000);
    float rowmax[8];
    #pragma unroll
    for (int r = 0; r < 8; ++r) rowmax[r] = NEG_INF;

    for (int mt = 0; mt < 2; ++mt) {
        const int m0 = mt * TILE;
        const float* B_base = s2 + ((size_t)(b * NL + m0 + ldl)) * ND + ldv;

        float acc[8][8];
        #pragma unroll
        for (int r = 0; r < 8; ++r)
            #pragma unroll
            for (int c = 0; c < 8; ++c) acc[r][c] = 0.f;

        // prefetch first K-slice
        float4 ra = *reinterpret_cast<const float4*>(A_base);
        float4 kv = *reinterpret_cast<const float4*>(kp);
        float4 rb = *reinterpret_cast<const float4*>(B_base);
        rb.x *= kv.x * kv.x; rb.y *= kv.y * kv.y;
        rb.z *= kv.z * kv.z; rb.w *= kv.w * kv.w;

        for (int kk = 0; kk < ND; kk += KSTEP) {
            __syncthreads();   // previous compute done with smem
            As[ldv + 0][ldl] = ra.x;
            As[ldv + 1][ldl] = ra.y;
            As[ldv + 2][ldl] = ra.z;
            As[ldv + 3][ldl] = ra.w;
            Bs[ldv + 0][ldl] = rb.x;
            Bs[ldv + 1][ldl] = rb.y;
            Bs[ldv + 2][ldl] = rb.z;
            Bs[ldv + 3][ldl] = rb.w;
            __syncthreads();

            if (kk + KSTEP < ND) {     // prefetch next slice under compute
                ra = *reinterpret_cast<const float4*>(A_base + kk + KSTEP);
                kv = *reinterpret_cast<const float4*>(kp + kk + KSTEP);
                rb = *reinterpret_cast<const float4*>(B_base + kk + KSTEP);
                rb.x *= kv.x * kv.x; rb.y *= kv.y * kv.y;
                rb.z *= kv.z * kv.z; rb.w *= kv.w * kv.w;
            }

            #pragma unroll
            for (int dk = 0; dk < KSTEP; ++dk) {
                float a[8], bb[8];
                float4 t;
                t = *reinterpret_cast<const float4*>(&As[dk][ty * 4]);
                a[0] = t.x; a[1] = t.y; a[2] = t.z; a[3] = t.w;
                t = *reinterpret_cast<const float4*>(&As[dk][64 + ty * 4]);
                a[4] = t.x; a[5] = t.y; a[6] = t.z; a[7] = t.w;
                t = *reinterpret_cast<const float4*>(&Bs[dk][tx * 4]);
                bb[0] = t.x; bb[1] = t.y; bb[2] = t.z; bb[3] = t.w;
                t = *reinterpret_cast<const float4*>(&Bs[dk][64 + tx * 4]);
                bb[4] = t.x; bb[5] = t.y; bb[6] = t.z; bb[7] = t.w;
                #pragma unroll
                for (int r = 0; r < 8; ++r)
                    #pragma unroll
                    for (int c = 0; c < 8; ++c)
                        acc[r][c] = fmaf(a[r], bb[c], acc[r][c]);
            }
        }

        // epilogue for this m-tile: scale by n2inv and fold into row max
        #pragma unroll
        for (int c = 0; c < 8; ++c) {
            const int m = m0 + ((c < 4) ? (tx * 4 + c) : (64 + tx * 4 + (c - 4)));
            const float n2 = g_n2inv[(size_t)(b * NL + m) * NP + p];
            #pragma unroll
            for (int r = 0; r < 8; ++r)
                rowmax[r] = fmaxf(rowmax[r], acc[r][c] * n2);
        }
    }

    // reduce max across tx (16-lane groups share the same rows)
    #pragma unroll
    for (int r = 0; r < 8; ++r) {
        float v = rowmax[r];
        v = fmaxf(v, __shfl_xor_sync(0xffffffffu, v, 8));
        v = fmaxf(v, __shfl_xor_sync(0xffffffffu, v, 4));
        v = fmaxf(v, __shfl_xor_sync(0xffffffffu, v, 2));
        v = fmaxf(v, __shfl_xor_sync(0xffffffffu, v, 1));
        rowmax[r] = v;
    }

    if (tx == 0) {
        #pragma unroll
        for (int r = 0; r < 8; ++r) {
            const int l = l0 + ((r < 4) ? (ty * 4 + r) : (64 + ty * 4 + (r - 4)));
            const size_t oi = (size_t)(b * NL + l) * NP + p;
            out[oi] = rowmax[r] * g_n1inv[oi];
        }
    }
}

// ---------------------------------------------------------------------------
extern "C" void kernel_launch(void* const* d_in, const int* in_sizes, int n_in,
                              void* d_out, int out_size)
{
    const float* s1   = (const float*)d_in[0];  // [16,256,256]
    const float* s2   = (const float*)d_in[1];  // [16,256,256]
    const float* kern = (const float*)d_in[2];  // [20,256]
    float* out = (float*)d_out;                 // [16,256,20]

    (void)in_sizes; (void)n_in; (void)out_size;

    // 1) inverse norms for both sentences: 2*16*256 rows, 1 warp/row, 8 warps/block
    norms_kernel<<<(2 * NB * NL) / 8, 256>>>(s1, s2, kern);

    // 2) fused GEMM + scale + max
    dim3 grid(NL / TILE, NP, NB);   // (2, 20, 16)
    mpm_kernel<<<grid, 256>>>(s1, s2, kern, out);
}

// round 5
// speedup vs baseline: 3.7487x; 3.7487x over previous
#include <cuda_runtime.h>
#include <cstdint>

// MaxPoolingMatching via mma.sync tf32 (base PTX — harness target is sm_103
// WITHOUT the 'a' suffix, so tcgen05/TMEM is unavailable; legacy tensor path it is).
//
//   num[b,l,m,p] = sum_d (s1[b,l,d]*k[p,d]^2) * s2[b,m,d]
//   out[b,l,p]   = n1inv[b,l,p] * max_m ( num * n2inv[b,m,p] )
//
// Per CTA (b, p, l-tile): 128x256x256 GEMM as 16 pipelined K-chunks
// (two 128-wide m-halves x 8 k-chunks of 32), cp.async double-buffered,
// ldmatrix fragments, k^2 applied to A fragments in registers,
// fused scale+max epilogue per m-half.

#define NB 16
#define NL 256
#define ND 256
#define NP 20

__device__ float g_n1inv[NB * NL * NP];
__device__ float g_n2inv[NB * NL * NP];

// ---------------------------------------------------------------------------
__device__ __forceinline__ uint32_t smem_u32(const void* p) {
    uint32_t a;
    asm("{ .reg .u64 t; cvta.to.shared.u64 t, %1; cvt.u32.u64 %0, t; }"
        : "=r"(a) : "l"(p));
    return a;
}

#define CP16(dst, src) \
    asm volatile("cp.async.cg.shared.global [%0], [%1], 16;" \
                 :: "r"(dst), "l"(src) : "memory")
#define CP_COMMIT() asm volatile("cp.async.commit_group;" ::: "memory")
#define CP_WAIT1()  asm volatile("cp.async.wait_group 1;" ::: "memory")
#define CP_WAIT0()  asm volatile("cp.async.wait_group 0;" ::: "memory")

#define LDSM4(r0, r1, r2, r3, a) \
    asm volatile("ldmatrix.sync.aligned.m8n8.x4.shared.b16 {%0,%1,%2,%3}, [%4];" \
                 : "=r"(r0), "=r"(r1), "=r"(r2), "=r"(r3) : "r"(a))

#define MMA_TF32(d, a, b0, b1) \
    asm volatile("mma.sync.aligned.m16n8k8.row.col.f32.tf32.tf32.f32 " \
                 "{%0,%1,%2,%3}, {%4,%5,%6,%7}, {%8,%9}, {%0,%1,%2,%3};" \
                 : "+f"((d)[0]), "+f"((d)[1]), "+f"((d)[2]), "+f"((d)[3]) \
                 : "r"((a)[0]), "r"((a)[1]), "r"((a)[2]), "r"((a)[3]), \
                   "r"(b0), "r"(b1))

// ---------------------------------------------------------------------------
// Kernel 1: inverse norms (unchanged — validated in R2)
// ---------------------------------------------------------------------------
__global__ void __launch_bounds__(256) norms_kernel(
    const float* __restrict__ s1,
    const float* __restrict__ s2,
    const float* __restrict__ kern)
{
    __shared__ float sk[NP * ND];
    const int tid = threadIdx.x;
    for (int i = 0; i < 20; ++i)
        sk[i * 256 + tid] = kern[i * 256 + tid];
    __syncthreads();

    const int lane = tid & 31;
    const int warp = tid >> 5;
    const int row  = blockIdx.x * 8 + warp;
    const int NR   = NB * NL;

    const float* src = (row < NR) ? (s1 + (size_t)row * ND)
                                  : (s2 + (size_t)(row - NR) * ND);
    float* dst = (row < NR) ? (g_n1inv + (size_t)row * NP)
                            : (g_n2inv + (size_t)(row - NR) * NP);

    const float4 v0 = *reinterpret_cast<const float4*>(src + lane * 4);
    const float4 v1 = *reinterpret_cast<const float4*>(src + 128 + lane * 4);

    for (int p = 0; p < NP; ++p) {
        const float* kp = sk + p * ND;
        const float4 k0 = *reinterpret_cast<const float4*>(kp + lane * 4);
        const float4 k1 = *reinterpret_cast<const float4*>(kp + 128 + lane * 4);
        float s = 0.f, t;
        t = v0.x * k0.x; s = fmaf(t, t, s);
        t = v0.y * k0.y; s = fmaf(t, t, s);
        t = v0.z * k0.z; s = fmaf(t, t, s);
        t = v0.w * k0.w; s = fmaf(t, t, s);
        t = v1.x * k1.x; s = fmaf(t, t, s);
        t = v1.y * k1.y; s = fmaf(t, t, s);
        t = v1.z * k1.z; s = fmaf(t, t, s);
        t = v1.w * k1.w; s = fmaf(t, t, s);
        #pragma unroll
        for (int o = 16; o > 0; o >>= 1)
            s += __shfl_xor_sync(0xffffffffu, s, o);
        if (lane == 0)
            dst[p] = rsqrtf(fmaxf(s, 1e-12f));
    }
}

// ---------------------------------------------------------------------------
// Kernel 2: tf32 mma.sync fused GEMM + scale + max
//
// Dynamic smem (1024-aligned base):
//   [0,1024)     kw[256]   = k[p,d]^2
//   [1024,2048)  n2sm[256] = n2inv[b,:,p]
//   [2048,4096)  part[4][128] cross-warp row-max
//   [4096..)     A0,A1,B0,B1 : each 128 rows x 32 fp32, row=128B, SW128 swizzle
// ---------------------------------------------------------------------------
#define OFF_KW   0
#define OFF_N2   1024
#define OFF_PART 2048
#define OFF_A0   4096
#define OFF_A1   (OFF_A0 + 16384)
#define OFF_B0   (OFF_A1 + 16384)
#define OFF_B1   (OFF_B0 + 16384)
#define SMEM_DYN (OFF_B1 + 16384 + 1024)

__global__ void __launch_bounds__(256, 2)
mpm_mma_kernel(const float* __restrict__ s1,
               const float* __restrict__ s2,
               const float* __restrict__ kern,
               float* __restrict__ out)
{
    extern __shared__ char dynraw[];
    char* base = (char*)(((uintptr_t)dynraw + 1023) & ~(uintptr_t)1023);

    float* kwsm = (float*)(base + OFF_KW);
    float* n2sm = (float*)(base + OFF_N2);
    float* part = (float*)(base + OFF_PART);

    const int b  = blockIdx.z;
    const int p  = blockIdx.y;
    const int l0 = blockIdx.x * 128;
    const int t  = threadIdx.x;
    const int lane = t & 31;
    const int warp = t >> 5;
    const int wm = warp >> 2;          // 0..1 : rows wm*64 .. +63
    const int wn = warp & 3;           // 0..3 : cols wn*32 .. +31

    const float NEG_INF = __int_as_float(0xff800000);

    // ---- stage kw / n2 / init part ----
    {
        const float v = kern[p * ND + t];
        kwsm[t] = v * v;
        n2sm[t] = g_n2inv[(size_t)(b * NL + t) * NP + p];
        part[t] = NEG_INF;
        part[t + 256] = NEG_INF;
    }

    // ---- staging mapping (cp.async 16B per op) ----
    const int rbase = t >> 3;          // 0..31
    const int f4    = t & 7;           // 16B column group
    const int cxor  = (f4 * 16) ^ ((rbase & 7) * 16);  // swizzled col bytes

    const size_t bNL = (size_t)b * NL;
    const float* Ag = s1 + (bNL + l0) * ND;
    const float* Bg = s2 + bNL * ND;

    const uint32_t uA[2] = { smem_u32(base + OFF_A0), smem_u32(base + OFF_A1) };
    const uint32_t uB[2] = { smem_u32(base + OFF_B0), smem_u32(base + OFF_B1) };

    auto stage = [&](int i) {
        const int kk = (i & 7) * 32;
        const int mb = (i >> 3) * 128;
        const uint32_t da = uA[i & 1] + rbase * 128 + cxor;
        const uint32_t db = uB[i & 1] + rbase * 128 + cxor;
        const float* ga = Ag + (size_t)rbase * ND + kk + f4 * 4;
        const float* gb = Bg + (size_t)(mb + rbase) * ND + kk + f4 * 4;
        #pragma unroll
        for (int pp = 0; pp < 4; ++pp) {
            CP16(da + pp * 4096, ga + (size_t)pp * 32 * ND);
            CP16(db + pp * 4096, gb + (size_t)pp * 32 * ND);
        }
        CP_COMMIT();
    };

    __syncthreads();   // kw/n2/part visible

    stage(0);
    stage(1);

    // ---- ldmatrix per-lane addressing ----
    const int arow = ((lane >> 3) & 1) * 8 + (lane & 7);
    const int acol = ((lane >> 4) & 1) * 16;
    const int brow = ((lane >> 4) & 1) * 8 + (lane & 7);
    const int bcol = ((lane >> 3) & 1) * 16;
    const int lxor = (lane & 7) * 16;

    float acc[4][4][4];
    #pragma unroll
    for (int i = 0; i < 4; ++i)
        #pragma unroll
        for (int j = 0; j < 4; ++j)
            #pragma unroll
            for (int r = 0; r < 4; ++r) acc[i][j][r] = 0.f;

    auto epilogue = [&](int mb) {
        #pragma unroll
        for (int i = 0; i < 4; ++i) {
            float v0 = NEG_INF, v1 = NEG_INF;
            #pragma unroll
            for (int j = 0; j < 4; ++j) {
                const int nb = mb + wn * 32 + (j >> 1) * 16 + (j & 1) * 8 + 2 * (lane & 3);
                const float sc0 = n2sm[nb], sc1 = n2sm[nb + 1];
                v0 = fmaxf(v0, fmaxf(acc[i][j][0] * sc0, acc[i][j][1] * sc1));
                v1 = fmaxf(v1, fmaxf(acc[i][j][2] * sc0, acc[i][j][3] * sc1));
            }
            v0 = fmaxf(v0, __shfl_xor_sync(0xffffffffu, v0, 1));
            v0 = fmaxf(v0, __shfl_xor_sync(0xffffffffu, v0, 2));
            v1 = fmaxf(v1, __shfl_xor_sync(0xffffffffu, v1, 1));
            v1 = fmaxf(v1, __shfl_xor_sync(0xffffffffu, v1, 2));
            if ((lane & 3) == 0) {
                const int row = wm * 64 + i * 16 + (lane >> 2);
                part[wn * 128 + row]     = fmaxf(part[wn * 128 + row], v0);
                part[wn * 128 + row + 8] = fmaxf(part[wn * 128 + row + 8], v1);
            }
        }
    };

    for (int i = 0; i < 16; ++i) {
        if (i < 14) CP_WAIT1(); else CP_WAIT0();
        __syncthreads();

        const uint32_t aBase = uA[i & 1] + (wm * 64 + arow) * 128;
        const uint32_t bBase = uB[i & 1] + (wn * 32 + brow) * 128;
        const int kk = (i & 7) * 32;

        #pragma unroll
        for (int ks = 0; ks < 4; ++ks) {
            uint32_t af[4][4];
            #pragma unroll
            for (int m16 = 0; m16 < 4; ++m16)
                LDSM4(af[m16][0], af[m16][1], af[m16][2], af[m16][3],
                      aBase + m16 * 2048 + ((ks * 32 + acol) ^ lxor));

            const float kw0 = kwsm[kk + ks * 8 + (lane & 3)];
            const float kw1 = kwsm[kk + ks * 8 + 4 + (lane & 3)];
            #pragma unroll
            for (int m16 = 0; m16 < 4; ++m16) {
                af[m16][0] = __float_as_uint(__uint_as_float(af[m16][0]) * kw0);
                af[m16][1] = __float_as_uint(__uint_as_float(af[m16][1]) * kw0);
                af[m16][2] = __float_as_uint(__uint_as_float(af[m16][2]) * kw1);
                af[m16][3] = __float_as_uint(__uint_as_float(af[m16][3]) * kw1);
            }

            uint32_t bf[2][4];
            #pragma unroll
            for (int pr = 0; pr < 2; ++pr)
                LDSM4(bf[pr][0], bf[pr][1], bf[pr][2], bf[pr][3],
                      bBase + pr * 2048 + ((ks * 32 + bcol) ^ lxor));

            #pragma unroll
            for (int m16 = 0; m16 < 4; ++m16)
                #pragma unroll
                for (int j = 0; j < 4; ++j)
                    MMA_TF32(acc[m16][j], af[m16],
                             bf[j >> 1][(j & 1) * 2], bf[j >> 1][(j & 1) * 2 + 1]);
        }

        __syncthreads();            // everyone done reading buffer (i&1)
        if (i + 2 < 16) stage(i + 2);

        if ((i & 7) == 7) {
            epilogue((i >> 3) * 128);
            if (i == 7) {
                #pragma unroll
                for (int a = 0; a < 4; ++a)
                    #pragma unroll
                    for (int j = 0; j < 4; ++j)
                        #pragma unroll
                        for (int r = 0; r < 4; ++r) acc[a][j][r] = 0.f;
            }
        }
    }

    __syncthreads();
    if (t < 128) {
        float v = fmaxf(fmaxf(part[t], part[128 + t]),
                        fmaxf(part[256 + t], part[384 + t]));
        const size_t oi = (size_t)(b * NL + l0 + t) * NP + p;
        out[oi] = v * g_n1inv[oi];
    }
}

// ---------------------------------------------------------------------------
extern "C" void kernel_launch(void* const* d_in, const int* in_sizes, int n_in,
                              void* d_out, int out_size)
{
    const float* s1   = (const float*)d_in[0];  // [16,256,256]
    const float* s2   = (const float*)d_in[1];  // [16,256,256]
    const float* kern = (const float*)d_in[2];  // [20,256]
    float* out = (float*)d_out;                 // [16,256,20]

    (void)in_sizes; (void)n_in; (void)out_size;

    cudaFuncSetAttribute(mpm_mma_kernel,
                         cudaFuncAttributeMaxDynamicSharedMemorySize, SMEM_DYN);

    norms_kernel<<<(2 * NB * NL) / 8, 256>>>(s1, s2, kern);

    dim3 grid(2, NP, NB);   // (l-tiles, P, B) = 640 CTAs
    mpm_mma_kernel<<<grid, 256, SMEM_DYN>>>(s1, s2, kern, out);
}